// round 3
// baseline (speedup 1.0000x reference)
#include <cuda_runtime.h>

#define T_DIM 4096
#define D_DIM 64
#define B_DIM 32

// One pyramid level, windows W = M .. 2M-1, k-descending streaming form.
//   coarse: res += pm[k] * sum_{p} w[p]*C[k-p]
//   fine:   res += pm[k] * F[k] * suf,  suf = suffix sum of w maintained as scalar
// F is read with compile-time stride FS (T_DIM for level 0 = rep in GMEM,
// 1 for register-resident levels). pm/dm are streamed, never array-resident.
template<int M, int FS>
__device__ __forceinline__ void level_k(const float* __restrict__ F,
                                        float* __restrict__ C,
                                        const float* __restrict__ pmb,
                                        const float* __restrict__ dmb,
                                        int low, int up, float& res)
{
    float w[M];
    float suf = 0.f;
#pragma unroll
    for (int k = 2 * M - 2; k >= 0; k--) {
        // lazy w load: w[p] first needed at k = p + M - 1
        if (k >= M - 1) {
            const int p = k - (M - 1);
            const int W = M + p;
            w[p] = (W >= low && W < up) ? dmb[(W - 1) * T_DIM] : 0.f;
        }
        // suffix-sum scalar: w[q] joins suf at k = 2q-1 (odd)
        if (k & 1) suf += w[(k + 1) / 2];
        // lazy C build: C[j] first needed at k = 2j
        if ((k & 1) == 0) C[k / 2] = 0.5f * (F[k * FS] + F[(k + 1) * FS]);
        float coef = 0.f;
        if (k <= 2 * M - 3) coef = F[k * FS] * suf;   // fine term
        const int pmin = (k - (M - 1) > 0) ? k - (M - 1) : 0;
        const int pmax = k / 2;
#pragma unroll
        for (int p = pmin; p <= pmax; p++)
            coef = fmaf(w[p], C[k - p], coef);        // coarse correlation
        res = fmaf(pmb[k * T_DIM], coef, res);
    }
}

__global__ __launch_bounds__(128, 8)
void ContextGenerator_34875134444049_kernel(const float* __restrict__ rep,
                                            const float* __restrict__ dmask,
                                            const float* __restrict__ pmask,
                                            const int* __restrict__ lowp,
                                            const int* __restrict__ upp,
                                            float* __restrict__ out)
{
    const int gid = blockIdx.x * 128 + threadIdx.x;   // 0 .. B*T-1
    const int b = gid >> 12;                          // T = 4096
    const int t = gid & (T_DIM - 1);
    const int base = b * (D_DIM * T_DIM) + t;

    const int low = *lowp;
    const int up  = *upp;

    const float* __restrict__ pmb = pmask + base;
    const float* __restrict__ dmb = dmask + base;

    float res = 0.f;

    float C1[32]; level_k<32, T_DIM>(rep + base, C1, pmb, dmb, low, up, res);
    float C2[16]; level_k<16, 1>(C1, C2, pmb, dmb, low, up, res);
    float C3[8];  level_k<8, 1>(C2, C3, pmb, dmb, low, up, res);
    float C4[4];  level_k<4, 1>(C3, C4, pmb, dmb, low, up, res);
    float C5[2];  level_k<2, 1>(C4, C5, pmb, dmb, low, up, res);

    // W = 1: d = deepest coarse level (single element)
    const float x6 = 0.5f * (C5[0] + C5[1]);
    if (1 >= low && 1 < up) res = fmaf(dmb[0], x6 * pmb[0], res);

    out[gid] = res;   // [B, 1, T] flat = gid
}

extern "C" void kernel_launch(void* const* d_in, const int* in_sizes, int n_in,
                              void* d_out, int out_size)
{
    const float* rep   = (const float*)d_in[0];
    const float* dmask = (const float*)d_in[1];
    const float* pmask = (const float*)d_in[2];
    const int*   lowp  = (const int*)d_in[3];
    const int*   upp   = (const int*)d_in[4];
    float* out = (float*)d_out;

    const int total = B_DIM * T_DIM;           // 131072
    ContextGenerator_34875134444049_kernel<<<total / 128, 128>>>(
        rep, dmask, pmask, lowp, upp, out);
}

// round 4
// speedup vs baseline: 1.3017x; 1.3017x over previous
#include <cuda_runtime.h>

#define T_DIM 4096
#define D_DIM 64
#define B_DIM 32

__device__ __forceinline__ void pf_l2(const float* p) {
    asm volatile("prefetch.global.L2 [%0];" :: "l"(p));
}

// Per-thread pyramid transition for level size M (coarse length M, fine length 2M).
template<int M>
__device__ __forceinline__ void transition(const float* __restrict__ F,
                                           float* __restrict__ C,
                                           const float* __restrict__ pmv,
                                           const float* __restrict__ dmb,
                                           int low, int up, float& res)
{
    float ft[M];
#pragma unroll
    for (int j = 0; j < M; j++) {
        float a = F[2 * j], b = F[2 * j + 1];
        C[j]  = 0.5f * (a + b);
        ft[j] = fmaf(a, pmv[2 * j], b * pmv[2 * j + 1]);
    }
    float suf = 0.f;
#pragma unroll
    for (int p = M - 1; p >= 1; p--) {
        const int W = M + p;
        float w = 0.f;
        if (W >= low && W < up) w = dmb[(W - 1) * T_DIM];
        float sc = 0.f;
#pragma unroll
        for (int j = p; j < M; j++) sc = fmaf(C[j], pmv[j + p], sc);
        res = fmaf(w, sc, res);
        suf += w;
        res = fmaf(ft[p - 1], suf, res);
    }
    {   // p = 0: exact window W = M
        float w = 0.f;
        if (M >= low && M < up) w = dmb[(M - 1) * T_DIM];
        float sc = 0.f;
#pragma unroll
        for (int j = 0; j < M; j++) sc = fmaf(C[j], pmv[j], sc);
        res = fmaf(w, sc, res);
    }
}

// First transition (M=32): fine level streamed straight from GMEM.
__device__ __forceinline__ void transition32_load(const float* __restrict__ repb,
                                                  float* __restrict__ C,
                                                  const float* __restrict__ pmv,
                                                  const float* __restrict__ dmb,
                                                  int low, int up, float& res)
{
    constexpr int M = 32;
    float ft[M];
#pragma unroll
    for (int j = 0; j < M; j++) {
        float a = repb[(2 * j) * T_DIM];
        float b = repb[(2 * j + 1) * T_DIM];
        C[j]  = 0.5f * (a + b);
        ft[j] = fmaf(a, pmv[2 * j], b * pmv[2 * j + 1]);
    }
    float suf = 0.f;
#pragma unroll
    for (int p = M - 1; p >= 1; p--) {
        const int W = M + p;
        float w = 0.f;
        if (W >= low && W < up) w = dmb[(W - 1) * T_DIM];
        float sc = 0.f;
#pragma unroll
        for (int j = p; j < M; j++) sc = fmaf(C[j], pmv[j + p], sc);
        res = fmaf(w, sc, res);
        suf += w;
        res = fmaf(ft[p - 1], suf, res);
    }
    {
        float w = 0.f;
        if (M >= low && M < up) w = dmb[(M - 1) * T_DIM];
        float sc = 0.f;
#pragma unroll
        for (int j = 0; j < M; j++) sc = fmaf(C[j], pmv[j], sc);
        res = fmaf(w, sc, res);
    }
}

__global__ __launch_bounds__(256)
void ContextGenerator_34875134444049_kernel(const float* __restrict__ rep,
                                            const float* __restrict__ dmask,
                                            const float* __restrict__ pmask,
                                            const int* __restrict__ lowp,
                                            const int* __restrict__ upp,
                                            float* __restrict__ out)
{
    const int gid = blockIdx.x * 256 + threadIdx.x;   // 0 .. B*T-1
    const int b = gid >> 12;                          // T = 4096
    const int t = gid & (T_DIM - 1);
    const int base = b * (D_DIM * T_DIM) + t;

    const float* __restrict__ repb = rep + base;
    const float* __restrict__ pmb  = pmask + base;
    const float* __restrict__ dmb  = dmask + base;

    // Fire-and-forget L2 prefetch of this thread's entire footprint.
    // No registers, no scoreboard slots -> unbounded MLP; working set
    // (~103 MB) fits L2 (126 MB), so real LDGs below see L2-hit latency.
#pragma unroll
    for (int r = 0; r < D_DIM; r++)     pf_l2(repb + r * T_DIM);
#pragma unroll
    for (int r = 0; r < D_DIM - 1; r++) pf_l2(pmb + r * T_DIM);
#pragma unroll
    for (int r = 0; r < D_DIM - 1; r++) pf_l2(dmb + r * T_DIM);

    const int low = *lowp;
    const int up  = *upp;

    float pmv[64];
#pragma unroll
    for (int w = 0; w < 64; w++) pmv[w] = pmb[w * T_DIM];

    float res = 0.f;

    float L1[32]; transition32_load(repb, L1, pmv, dmb, low, up, res);
    float L2[16]; transition<16>(L1, L2, pmv, dmb, low, up, res);
    float L3[8];  transition<8>(L2, L3, pmv, dmb, low, up, res);
    float L4[4];  transition<4>(L3, L4, pmv, dmb, low, up, res);
    float L5[2];  transition<2>(L4, L5, pmv, dmb, low, up, res);

    // W = 1
    const float x6 = 0.5f * (L5[0] + L5[1]);
    if (1 >= low && 1 < up) res = fmaf(dmb[0], x6 * pmv[0], res);

    out[gid] = res;   // [B, 1, T] flat = gid
}

extern "C" void kernel_launch(void* const* d_in, const int* in_sizes, int n_in,
                              void* d_out, int out_size)
{
    const float* rep   = (const float*)d_in[0];
    const float* dmask = (const float*)d_in[1];
    const float* pmask = (const float*)d_in[2];
    const int*   lowp  = (const int*)d_in[3];
    const int*   upp   = (const int*)d_in[4];
    float* out = (float*)d_out;

    const int total = B_DIM * T_DIM;           // 131072
    ContextGenerator_34875134444049_kernel<<<total / 256, 256>>>(
        rep, dmask, pmask, lowp, upp, out);
}